// round 17
// baseline (speedup 1.0000x reference)
#include <cuda_runtime.h>

// Problem constants
constexpr int Nn = 4096;   // nodes
constexpr int Dd = 256;    // model dim
constexpr int Ee = 65536;  // edges
constexpr int DCAP = 64;   // per-row bucket capacity

// Fragment-linear GEMM: BM=64/BN=128, 128 thr, 4 warps, warp-tile 64x32.
// 2 k-tiles per stage, 3-buffer ring, ONE barrier per stage.
constexpr int STG_FLOATS = 6144;                      // 2 x (1024 A + 2048 W)
constexpr int NSTG = 8;                               // 16 k-tiles / 2
constexpr int GEMM_SMEM_BYTES = 3 * STG_FLOATS * 4;   // 73728

// ---------------------------------------------------------------------------
// Scratch
// ---------------------------------------------------------------------------
__device__ float    g_Q[Nn * Dd];
__device__ float    g_KV[Nn * 512];     // row: [K(256) | V(256)] interleaved
__device__ float    g_attnp[Nn * Dd];   // attn in A-fragment-linear layout
__device__ float    g_vsum[Dd];
__device__ int      g_cnt[Nn];
__device__ int      g_adj[Nn * DCAP];
// permuted (fragment-linear) tf32-rounded operands
__device__ float    g_xp[Nn * Dd];
__device__ float    g_Wqp[Dd * Dd];
__device__ float    g_Wkp[Dd * Dd];
__device__ float    g_Wvp[Dd * Dd];
__device__ float    g_Wop[Dd * Dd];

// ---------------------------------------------------------------------------
__device__ __forceinline__ float tf32_rna(float f) {
    unsigned u;
    asm("cvt.rna.tf32.f32 %0, %1;" : "=r"(u) : "f"(f));
    return __uint_as_float(u);
}

__global__ void bucket_kernel(const int* __restrict__ ei) {
    int e = blockIdx.x * blockDim.x + threadIdx.x;
    if (e >= Ee) return;
    int row = ei[e] & (Nn - 1);
    int col = ei[Ee + e] & (Nn - 1);
    int p = atomicAdd(&g_cnt[row], 1);
    if (p < DCAP) g_adj[row * DCAP + p] = col;
}

// ---------------------------------------------------------------------------
// Permute + tf32-round pass; also zeroes g_cnt / g_vsum.
// ---------------------------------------------------------------------------
__global__ void permute_kernel(const float* __restrict__ x,
                               const float* __restrict__ Wq,
                               const float* __restrict__ Wk,
                               const float* __restrict__ Wv,
                               const float* __restrict__ Wo) {
    int idx = blockIdx.x * blockDim.x + threadIdx.x;
    int stride = gridDim.x * blockDim.x;

    if (idx < Nn) g_cnt[idx] = 0;
    if (idx < Dd) g_vsum[idx] = 0.0f;

    for (int cidx = idx; cidx < Nn * Dd / 4; cidx += stride) {
        int lane   = cidx & 31;
        int kk     = (cidx >> 5) & 1;
        int mblk   = (cidx >> 6) & 7;
        int kblk   = (cidx >> 9) & 15;
        int mpanel = cidx >> 13;
        int m = mpanel * 128 + mblk * 16 + (lane >> 2);
        int k = kblk * 16 + kk * 8 + (lane & 3);
        float4 v;
        v.x = tf32_rna(x[(size_t)m * Dd + k]);
        v.y = tf32_rna(x[(size_t)(m + 8) * Dd + k]);
        v.z = tf32_rna(x[(size_t)m * Dd + k + 4]);
        v.w = tf32_rna(x[(size_t)(m + 8) * Dd + k + 4]);
        ((float4*)g_xp)[cidx] = v;
    }

    for (int cidx = idx; cidx < Dd * Dd / 4; cidx += stride) {
        int lane   = cidx & 31;
        int nblk   = (cidx >> 5) & 15;
        int kblk   = (cidx >> 9) & 15;
        int npanel = cidx >> 13;
        int n  = npanel * 128 + nblk * 8 + (lane >> 2);
        int kb = kblk * 16 + (lane & 3);
        size_t s = (size_t)n * Dd + kb;
        float4 vq, vk, vv, vo;
        vq.x = tf32_rna(Wq[s]);      vq.y = tf32_rna(Wq[s + 4]);
        vq.z = tf32_rna(Wq[s + 8]);  vq.w = tf32_rna(Wq[s + 12]);
        vk.x = tf32_rna(Wk[s]);      vk.y = tf32_rna(Wk[s + 4]);
        vk.z = tf32_rna(Wk[s + 8]);  vk.w = tf32_rna(Wk[s + 12]);
        vv.x = tf32_rna(Wv[s]);      vv.y = tf32_rna(Wv[s + 4]);
        vv.z = tf32_rna(Wv[s + 8]);  vv.w = tf32_rna(Wv[s + 12]);
        vo.x = tf32_rna(Wo[s]);      vo.y = tf32_rna(Wo[s + 4]);
        vo.z = tf32_rna(Wo[s + 8]);  vo.w = tf32_rna(Wo[s + 12]);
        ((float4*)g_Wqp)[cidx] = vq;
        ((float4*)g_Wkp)[cidx] = vk;
        ((float4*)g_Wvp)[cidx] = vv;
        ((float4*)g_Wop)[cidx] = vo;
    }
}

// ---------------------------------------------------------------------------
// Shared GEMM helpers
// ---------------------------------------------------------------------------
__device__ __forceinline__ unsigned smem_u32(const void* p) {
    return (unsigned)__cvta_generic_to_shared(p);
}
__device__ __forceinline__ void cp_async16(unsigned dst, const void* src) {
    asm volatile("cp.async.cg.shared.global [%0], [%1], 16;" :: "r"(dst), "l"(src));
}
__device__ __forceinline__ void cp_commit() {
    asm volatile("cp.async.commit_group;" ::: "memory");
}
template <int N> __device__ __forceinline__ void cp_wait() {
    asm volatile("cp.async.wait_group %0;" :: "n"(N) : "memory");
}
__device__ __forceinline__ void mma_tf32(float* d, float a0, float a1, float a2, float a3,
                                         float b0, float b1) {
    asm volatile(
        "mma.sync.aligned.m16n8k8.row.col.f32.tf32.tf32.f32 "
        "{%0,%1,%2,%3}, {%4,%5,%6,%7}, {%8,%9}, {%0,%1,%2,%3};\n"
        : "+f"(d[0]), "+f"(d[1]), "+f"(d[2]), "+f"(d[3])
        : "r"(__float_as_uint(a0)), "r"(__float_as_uint(a1)),
          "r"(__float_as_uint(a2)), "r"(__float_as_uint(a3)),
          "r"(__float_as_uint(b0)), "r"(__float_as_uint(b1)));
}

// ---------------------------------------------------------------------------
// Fragment-linear GEMM body: 2 k-tiles/stage, 3-buffer ring, 1 barrier/stage.
// ldc/coff parameterize the output (g_KV interleaving for K and V).
// ---------------------------------------------------------------------------
template <bool FUSE_VSUM, bool BIAS>
__device__ __forceinline__ void gemm_frag_body(const float* __restrict__ Ap,
                                               const float* __restrict__ Wp,
                                               const float* __restrict__ bias,
                                               float* __restrict__ C,
                                               int ldc, int coff,
                                               int by, int bx) {
    extern __shared__ __align__(16) float smem[];
    const int tid  = threadIdx.x;
    const int lane = tid & 31;
    const int wid  = tid >> 5;          // 0..3 -> n-block group
    const unsigned sbase = smem_u32(smem);

    const int mp128 = by >> 1;
    const int half  = by & 1;

    float d[4][4][4];
#pragma unroll
    for (int i = 0; i < 4; i++)
#pragma unroll
        for (int j = 0; j < 4; j++)
#pragma unroll
            for (int q = 0; q < 4; q++) d[i][j][q] = 0.0f;

    auto stage = [&](int st) {
        unsigned base = sbase + (unsigned)((st % 3) * STG_FLOATS) * 4u;
#pragma unroll
        for (int kt = 0; kt < 2; kt++) {
            int t = 2 * st + kt;
            unsigned dstA = base + kt * 3072 * 4;
            const float* srcA = Ap + ((size_t)mp128 * 16 + t) * 2048 + half * 1024;
            cp_async16(dstA + tid * 16, srcA + (size_t)tid * 4);
            cp_async16(dstA + (tid + 128) * 16, srcA + (size_t)(tid + 128) * 4);
            unsigned dstW = dstA + 1024 * 4;
            const float* srcW = Wp + ((size_t)bx * 16 + t) * 2048;
            cp_async16(dstW + tid * 16, srcW + (size_t)tid * 4);
            cp_async16(dstW + (tid + 128) * 16, srcW + (size_t)(tid + 128) * 4);
            cp_async16(dstW + (tid + 256) * 16, srcW + (size_t)(tid + 256) * 4);
            cp_async16(dstW + (tid + 384) * 16, srcW + (size_t)(tid + 384) * 4);
        }
        cp_commit();
    };

    stage(0); stage(1); stage(2);

    for (int st = 0; st < NSTG; st++) {
        if (st < NSTG - 1) cp_wait<1>();
        else               cp_wait<0>();
        __syncthreads();
        if (st >= 1 && st + 2 < NSTG) stage(st + 2);

#pragma unroll
        for (int kt = 0; kt < 2; kt++) {
            const float4* As4 = (const float4*)(smem + (st % 3) * STG_FLOATS + kt * 3072);
            const float4* Ws4 = (const float4*)(smem + (st % 3) * STG_FLOATS + kt * 3072 + 1024);

            float4 bv[4];
#pragma unroll
            for (int j = 0; j < 4; j++)
                bv[j] = Ws4[(wid * 4 + j) * 32 + lane];

#pragma unroll
            for (int kk = 0; kk < 2; kk++) {
                float4 av[4];
#pragma unroll
                for (int i = 0; i < 4; i++)
                    av[i] = As4[(i * 2 + kk) * 32 + lane];
#pragma unroll
                for (int i = 0; i < 4; i++)
#pragma unroll
                    for (int j = 0; j < 4; j++)
                        mma_tf32(d[i][j], av[i].x, av[i].y, av[i].z, av[i].w,
                                 kk ? bv[j].z : bv[j].x, kk ? bv[j].w : bv[j].y);
            }
        }
    }

    // Epilogue
    const int r = lane >> 2, c = lane & 3;
    const int m0 = by * 64;
    const int n0 = bx * 128 + wid * 32;
#pragma unroll
    for (int i = 0; i < 4; i++) {
#pragma unroll
        for (int j = 0; j < 4; j++) {
            int m = m0 + 16 * i + r;
            int n = n0 + 8 * j + 2 * c;
            float2 v0 = make_float2(d[i][j][0], d[i][j][1]);
            float2 v1 = make_float2(d[i][j][2], d[i][j][3]);
            if (BIAS) {
                float bx_ = bias[n], by_ = bias[n + 1];
                v0.x += bx_; v0.y += by_;
                v1.x += bx_; v1.y += by_;
            }
            *(float2*)&C[(size_t)m * ldc + coff + n] = v0;
            *(float2*)&C[(size_t)(m + 8) * ldc + coff + n] = v1;
        }
    }

    if (FUSE_VSUM) {
        float cs[8];
#pragma unroll
        for (int j = 0; j < 4; j++) {
            float s0 = 0.0f, s1 = 0.0f;
#pragma unroll
            for (int i = 0; i < 4; i++) {
                s0 += d[i][j][0] + d[i][j][2];
                s1 += d[i][j][1] + d[i][j][3];
            }
            cs[2 * j] = s0; cs[2 * j + 1] = s1;
        }
#pragma unroll
        for (int off = 4; off < 32; off <<= 1)
#pragma unroll
            for (int t2 = 0; t2 < 8; t2++)
                cs[t2] += __shfl_xor_sync(0xffffffffu, cs[t2], off);
        if (r == 0) {
#pragma unroll
            for (int j = 0; j < 4; j++) {
                atomicAdd(&g_vsum[n0 + 8 * j + 2 * c], cs[2 * j]);
                atomicAdd(&g_vsum[n0 + 8 * j + 2 * c + 1], cs[2 * j + 1]);
            }
        }
    }
}

__global__ __launch_bounds__(128, 3) void gemm_qkv_kernel() {
    if (blockIdx.z == 0)
        gemm_frag_body<false, false>(g_xp, g_Wqp, nullptr, g_Q, Dd, 0,
                                     blockIdx.y, blockIdx.x);
    else if (blockIdx.z == 1)
        gemm_frag_body<false, false>(g_xp, g_Wkp, nullptr, g_KV, 512, 0,
                                     blockIdx.y, blockIdx.x);
    else
        gemm_frag_body<true, false>(g_xp, g_Wvp, nullptr, g_KV, 512, 256,
                                    blockIdx.y, blockIdx.x);
}

__global__ __launch_bounds__(128, 3) void gemm_out_kernel(const float* __restrict__ bo,
                                                          float* __restrict__ out) {
    gemm_frag_body<false, true>(g_attnp, g_Wop, bo, out, Dd, 0,
                                blockIdx.y, blockIdx.x);
}

// ---------------------------------------------------------------------------
// Row kernel: 512 threads = 16 warps, one warp per row. Dedup -> compacted
// smem col list (no per-iteration shfl chain: next loads hoistable), single
// KV base per edge (interleaved layout). Writes g_attnp fragment-linear.
// ---------------------------------------------------------------------------
__global__ __launch_bounds__(512) void row_kernel() {
    __shared__ float att_s[16 * 260];   // pitch 260 -> conflict-free chunk reads
    __shared__ int   s_cols[16][DCAP];

    const int tid  = threadIdx.x;
    const int lane = tid & 31;
    const int wid  = tid >> 5;                 // 0..15: row within block
    const int row  = blockIdx.x * 16 + wid;

    const int deg = min(g_cnt[row], DCAP);
    const int* adj = g_adj + row * DCAP;

    int col0 = (lane < deg)      ? adj[lane]      : (-1 - lane);
    int col1 = (32 + lane < deg) ? adj[32 + lane] : (-1 - lane);

    unsigned m0 = __match_any_sync(0xffffffffu, col0);
    bool keep0 = (lane < deg) && (lane == __ffs(m0) - 1);
    unsigned bm0 = __ballot_sync(0xffffffffu, keep0);

    unsigned bm1 = 0u;
    if (deg > 32) {
        unsigned m1 = __match_any_sync(0xffffffffu, col1);
        bool keep1 = (32 + lane < deg) && (lane == __ffs(m1) - 1);
        for (int j = 0; j < 32; j++) {
            int cj = __shfl_sync(0xffffffffu, col0, j);
            if (j < deg && cj == col1) keep1 = false;
        }
        bm1 = __ballot_sync(0xffffffffu, keep1);
    }

    // Compact kept cols into the warp's smem list
    int c0n = __popc(bm0);
    if (keep0) s_cols[wid][__popc(bm0 & ((1u << lane) - 1))] = col0;
    if (bm1) {
        bool k1 = (bm1 >> lane) & 1;
        if (k1) s_cols[wid][c0n + __popc(bm1 & ((1u << lane) - 1))] = col1;
    }
    const int cnt = c0n + __popc(bm1);
    __syncwarp();

    float q[8];
    {
        const float* qp = g_Q + (size_t)row * Dd + lane * 8;
        float4 a = *(const float4*)qp;
        float4 b = *(const float4*)(qp + 4);
        q[0] = a.x; q[1] = a.y; q[2] = a.z; q[3] = a.w;
        q[4] = b.x; q[5] = b.y; q[6] = b.z; q[7] = b.w;
    }

    float acc[8] = {0, 0, 0, 0, 0, 0, 0, 0};
    float dn = 0.0f;
    const int lane8 = lane * 8;
    const float inv_scale = 0.17677669529663687f;  // 1/sqrt(32)

#pragma unroll 1
    for (int j = 0; j < cnt; j += 2) {
        int cA = s_cols[wid][j];
        bool hasB = (j + 1 < cnt);                 // warp-uniform
        int cB = hasB ? s_cols[wid][j + 1] : cA;

        const float* pA = g_KV + ((size_t)cA << 9) + lane8;
        const float* pB = g_KV + ((size_t)cB << 9) + lane8;
        float4 kA1 = *(const float4*)pA;
        float4 kA2 = *(const float4*)(pA + 4);
        float4 vA1 = *(const float4*)(pA + 256);
        float4 vA2 = *(const float4*)(pA + 260);
        float4 kB1 = *(const float4*)pB;
        float4 kB2 = *(const float4*)(pB + 4);
        float4 vB1 = *(const float4*)(pB + 256);
        float4 vB2 = *(const float4*)(pB + 260);

        float sA = q[0]*kA1.x + q[1]*kA1.y + q[2]*kA1.z + q[3]*kA1.w
                 + q[4]*kA2.x + q[5]*kA2.y + q[6]*kA2.z + q[7]*kA2.w;
        float sB = q[0]*kB1.x + q[1]*kB1.y + q[2]*kB1.z + q[3]*kB1.w
                 + q[4]*kB2.x + q[5]*kB2.y + q[6]*kB2.z + q[7]*kB2.w;
        sA += __shfl_xor_sync(0xffffffffu, sA, 1);
        sB += __shfl_xor_sync(0xffffffffu, sB, 1);
        sA += __shfl_xor_sync(0xffffffffu, sA, 2);
        sB += __shfl_xor_sync(0xffffffffu, sB, 2);
        float wA = __expf(sA * inv_scale) - 1.0f;
        float wB = hasB ? (__expf(sB * inv_scale) - 1.0f) : 0.0f;

        acc[0] += wA*vA1.x + wB*vB1.x; acc[1] += wA*vA1.y + wB*vB1.y;
        acc[2] += wA*vA1.z + wB*vB1.z; acc[3] += wA*vA1.w + wB*vB1.w;
        acc[4] += wA*vA2.x + wB*vB2.x; acc[5] += wA*vA2.y + wB*vB2.y;
        acc[6] += wA*vA2.z + wB*vB2.z; acc[7] += wA*vA2.w + wB*vB2.w;
        dn += wA + wB;
    }

    // Stage att row into smem (tf32-rounded: feeds the tf32 out-GEMM)
    const float* vs = g_vsum + lane8;
    float inv_d = 1.0f / ((float)Nn + dn);
    float* arow = att_s + wid * 260 + lane8;
#pragma unroll
    for (int i = 0; i < 8; i++)
        arow[i] = tf32_rna((vs[i] + acc[i]) * inv_d);
    __syncthreads();

    // Write A-fragment-linear chunks: 1024 float4 per block, 2 per thread.
    const int mpanel = blockIdx.x >> 3;
    const int mblk   = blockIdx.x & 7;
#pragma unroll
    for (int ci = tid; ci < 1024; ci += 512) {
        int lane_c = ci & 31;
        int kk     = (ci >> 5) & 1;
        int kblk   = ci >> 6;
        int mloc   = lane_c >> 2;
        int k      = kblk * 16 + kk * 8 + (lane_c & 3);
        float4 v;
        v.x = att_s[mloc * 260 + k];
        v.y = att_s[(mloc + 8) * 260 + k];
        v.z = att_s[mloc * 260 + k + 4];
        v.w = att_s[(mloc + 8) * 260 + k + 4];
        size_t g = ((((size_t)mpanel * 16 + kblk) * 8 + mblk) * 2 + kk) * 32 + lane_c;
        ((float4*)g_attnp)[g] = v;
    }
}

// ---------------------------------------------------------------------------
extern "C" void kernel_launch(void* const* d_in, const int* in_sizes, int n_in,
                              void* d_out, int out_size) {
    const float* x  = (const float*)d_in[0];
    const int*   ei = (const int*)d_in[1];     // int32 (JAX x64 disabled)
    const float* Wq = (const float*)d_in[2];
    const float* Wk = (const float*)d_in[3];
    const float* Wv = (const float*)d_in[4];
    const float* Wo = (const float*)d_in[5];
    const float* bo = (const float*)d_in[6];
    float*       out = (float*)d_out;

    cudaFuncSetAttribute(gemm_qkv_kernel,
                         cudaFuncAttributeMaxDynamicSharedMemorySize, GEMM_SMEM_BYTES);
    cudaFuncSetAttribute(gemm_out_kernel,
                         cudaFuncAttributeMaxDynamicSharedMemorySize, GEMM_SMEM_BYTES);

    permute_kernel<<<512, 256>>>(x, Wq, Wk, Wv, Wo);   // also zeroes cnt/vsum
    bucket_kernel<<<Ee / 256, 256>>>(ei);
    gemm_qkv_kernel<<<dim3(2, 64, 3), 128, GEMM_SMEM_BYTES>>>();
    row_kernel<<<Nn / 16, 512>>>();
    gemm_out_kernel<<<dim3(2, 64, 1), 128, GEMM_SMEM_BYTES>>>(bo, out);
}